// round 6
// baseline (speedup 1.0000x reference)
#include <cuda_runtime.h>
#include <cuda_bf16.h>
#include <math.h>
#include <stdint.h>

#define Bb 2
#define Cc 512
#define Tt 16
#define NN 1024
#define HEADS 8
#define Dd 64
#define BT 32
#define C3 1536

typedef __nv_bfloat16 bf16;

// ---------------- scratch (device globals) ----------------
__device__ __align__(16) bf16  g_wsqkv_t[Cc * C3];   // Wt[k][o] bf16
__device__ __align__(16) bf16  g_wsout_t[Cc * Cc];
__device__ __align__(16) bf16  g_wtqkv_t[Cc * C3];
__device__ __align__(16) bf16  g_wtout_t[Cc * Cc];
__device__ __align__(16) bf16  g_xbf[Bb * Cc * Tt * NN];
__device__ __align__(16) bf16  g_sqkv[BT * C3 * NN];
__device__ __align__(16) bf16  g_ctx_ed[BT * HEADS * Dd * Dd];
__device__ __align__(16) bf16  g_sattn_bf[BT * Cc * NN];
__device__ __align__(16) bf16  g_h1_bf[Bb * Cc * Tt * NN];
__device__ __align__(16) bf16  g_tqkv[Bb * C3 * Tt * NN];
__device__ __align__(16) float g_attnw[Bb * HEADS * Tt * Tt * NN];
__device__ __align__(16) bf16  g_tout_bf[Bb * Cc * Tt * NN];

// ---------------- helpers ----------------
__device__ __forceinline__ uint32_t smem_u32(const void* p) {
    uint32_t a;
    asm("{ .reg .u64 t; cvta.to.shared.u64 t, %1; cvt.u32.u64 %0, t; }" : "=r"(a) : "l"(p));
    return a;
}
#define CP_ASYNC(dst, src) asm volatile("cp.async.cg.shared.global [%0],[%1],16;\n" :: "r"(dst), "l"(src) : "memory")
#define CP_COMMIT()        asm volatile("cp.async.commit_group;\n" ::: "memory")
#define CP_WAIT0()         asm volatile("cp.async.wait_group 0;\n" ::: "memory")
#define CP_WAIT1()         asm volatile("cp.async.wait_group 1;\n" ::: "memory")

#define LDSM_X4(r0,r1,r2,r3,addr) \
    asm volatile("ldmatrix.sync.aligned.m8n8.x4.shared.b16 {%0,%1,%2,%3},[%4];" \
                 : "=r"(r0),"=r"(r1),"=r"(r2),"=r"(r3) : "r"(addr))
#define LDSM_X4T(r0,r1,r2,r3,addr) \
    asm volatile("ldmatrix.sync.aligned.m8n8.x4.trans.shared.b16 {%0,%1,%2,%3},[%4];" \
                 : "=r"(r0),"=r"(r1),"=r"(r2),"=r"(r3) : "r"(addr))
#define LDSM_X2T(r0,r1,addr) \
    asm volatile("ldmatrix.sync.aligned.m8n8.x2.trans.shared.b16 {%0,%1},[%2];" \
                 : "=r"(r0),"=r"(r1) : "r"(addr))
#define MMA16816(d0,d1,d2,d3,a0,a1,a2,a3,b0,b1) \
    asm volatile("mma.sync.aligned.m16n8k16.row.col.f32.bf16.bf16.f32 " \
                 "{%0,%1,%2,%3},{%4,%5,%6,%7},{%8,%9},{%0,%1,%2,%3};" \
                 : "+f"(d0),"+f"(d1),"+f"(d2),"+f"(d3) \
                 : "r"(a0),"r"(a1),"r"(a2),"r"(a3),"r"(b0),"r"(b1))

// ---------------- conversions ----------------
__global__ void f2b_kernel(const float* __restrict__ in, bf16* __restrict__ out, int n)
{
    int i = (blockIdx.x * blockDim.x + threadIdx.x) * 4;
    if (i < n) {
        float4 v = *(const float4*)(in + i);
        __nv_bfloat162 p0 = __floats2bfloat162_rn(v.x, v.y);
        __nv_bfloat162 p1 = __floats2bfloat162_rn(v.z, v.w);
        uint2 u;
        u.x = *(uint32_t*)&p0;
        u.y = *(uint32_t*)&p1;
        *(uint2*)(out + i) = u;
    }
}

__global__ void transpose_w_kernel(const float* __restrict__ in, bf16* __restrict__ out,
                                   int O, int K)
{
    int idx = blockIdx.x * blockDim.x + threadIdx.x;
    if (idx < O * K) {
        int o = idx % O;
        int k = idx / O;
        out[idx] = __float2bfloat16(in[(long long)o * K + k]);
    }
}

// ---------------- bf16 tensor-core GEMM: 128(o) x 256(n) x 32k tiles ----------------
// C[g][o][n] = sum_k Wt[k][o] * X[g][k][n]
// 8 warps: wm = warp>>2 (m64), wn = warp&3 (n64). 3-stage cp.async pipeline.
// smem per stage: A [32k][128o] = 8KB, B [32k][256n] = 16KB.
#define GSTAGE 24576
#define GSMEM  (3 * GSTAGE)

__global__ __launch_bounds__(256, 1) void gemm_bf16(
    const bf16* __restrict__ Wt,   // [K][ldA]
    const bf16* __restrict__ X,
    float* __restrict__ Cf,
    bf16* __restrict__ Cb,
    const float* __restrict__ bias,
    const float* __restrict__ res,
    int K, int ldA, int gDiv,
    long long xOuter, long long xInner, long long xRow,
    long long cOuter, long long cInner, long long cRow)
{
    extern __shared__ bf16 gsm[];
    uint32_t sb = smem_u32(gsm);

    int g = blockIdx.z;
    long long gq = g / gDiv, gr = g % gDiv;
    const bf16* Xb = X + gq * xOuter + gr * xInner;
    long long cbase = gq * cOuter + gr * cInner;

    int n0 = blockIdx.x * 256;
    int o0 = blockIdx.y * 128;

    int tid = threadIdx.x;
    int lane = tid & 31, warp = tid >> 5;
    int wm = warp >> 2, wn = warp & 3;

    float acc[4][8][4];
    #pragma unroll
    for (int a = 0; a < 4; a++)
        #pragma unroll
        for (int b = 0; b < 8; b++)
            #pragma unroll
            for (int c = 0; c < 4; c++) acc[a][b][c] = 0.f;

    int nkt = K / 32;

    // stage layout: A at s*GSTAGE, B at s*GSTAGE + 8192
    #define ISSUE_TILE(kt, s) do {                                                       \
        int k0_ = (kt) * 32;                                                             \
        uint32_t ab_ = sb + (s) * GSTAGE;                                                \
        uint32_t bb_ = ab_ + 8192;                                                       \
        _Pragma("unroll")                                                                \
        for (int i_ = 0; i_ < 2; i_++) {                                                 \
            int idx_ = tid + 256 * i_;                                                   \
            int row_ = idx_ >> 4, ch_ = idx_ & 15;                                       \
            const bf16* sA = Wt + (long long)(k0_ + row_) * ldA + o0 + ch_ * 8;          \
            uint32_t dA = ab_ + row_ * 256 + (((ch_) ^ (row_ & 7)) << 4);                \
            CP_ASYNC(dA, sA);                                                            \
        }                                                                                \
        _Pragma("unroll")                                                                \
        for (int i_ = 0; i_ < 4; i_++) {                                                 \
            int idx_ = tid + 256 * i_;                                                   \
            int row_ = idx_ >> 5, ch_ = idx_ & 31;                                       \
            const bf16* sB = Xb + (long long)(k0_ + row_) * xRow + n0 + ch_ * 8;         \
            uint32_t dB = bb_ + row_ * 512 + (((ch_) ^ (row_ & 7)) << 4);                \
            CP_ASYNC(dB, sB);                                                            \
        }                                                                                \
    } while (0)

    ISSUE_TILE(0, 0);
    CP_COMMIT();
    ISSUE_TILE(1, 1);
    CP_COMMIT();

    int r7 = lane & 7, sub = lane >> 3;

    for (int kt = 0; kt < nkt; kt++) {
        if (kt + 1 < nkt) CP_WAIT1(); else CP_WAIT0();
        __syncthreads();
        if (kt + 2 < nkt) {
            ISSUE_TILE(kt + 2, (kt + 2) % 3);
            CP_COMMIT();
        }
        uint32_t abase = sb + (kt % 3) * GSTAGE;
        uint32_t bbase = abase + 8192;

        #pragma unroll
        for (int ks = 0; ks < 2; ks++) {
            uint32_t af[4][4];
            #pragma unroll
            for (int mt = 0; mt < 4; mt++) {
                int krow = ks * 16 + r7 + ((sub >> 1) << 3);
                int mcol = wm * 64 + mt * 16 + ((sub & 1) << 3);
                uint32_t addr = abase + krow * 256 + ((((mcol >> 3)) ^ (krow & 7)) << 4);
                LDSM_X4T(af[mt][0], af[mt][1], af[mt][2], af[mt][3], addr);
            }
            #pragma unroll
            for (int nt2 = 0; nt2 < 4; nt2++) {
                int brow = ks * 16 + (lane & 15);
                int nch  = ((wn * 64 + nt2 * 16) >> 3) + (lane >> 4);
                uint32_t addr = bbase + brow * 512 + ((nch ^ (brow & 7)) << 4);
                uint32_t b0, b1, b2, b3;
                LDSM_X4T(b0, b1, b2, b3, addr);
                #pragma unroll
                for (int mt = 0; mt < 4; mt++) {
                    MMA16816(acc[mt][nt2*2][0],   acc[mt][nt2*2][1],
                             acc[mt][nt2*2][2],   acc[mt][nt2*2][3],
                             af[mt][0], af[mt][1], af[mt][2], af[mt][3], b0, b1);
                    MMA16816(acc[mt][nt2*2+1][0], acc[mt][nt2*2+1][1],
                             acc[mt][nt2*2+1][2], acc[mt][nt2*2+1][3],
                             af[mt][0], af[mt][1], af[mt][2], af[mt][3], b2, b3);
                }
            }
        }
        __syncthreads();
    }

    int g4 = lane >> 2, t4 = lane & 3;
    #pragma unroll
    for (int mt = 0; mt < 4; mt++) {
        #pragma unroll
        for (int nt = 0; nt < 8; nt++) {
            int orow = o0 + wm * 64 + mt * 16 + g4;
            int col  = n0 + wn * 64 + nt * 8 + t4 * 2;
            long long off0 = cbase + (long long)orow * cRow + col;
            long long off1 = off0 + 8 * cRow;
            float b0 = bias ? bias[orow] : 0.f;
            float b1 = bias ? bias[orow + 8] : 0.f;
            float* a = acc[mt][nt];
            if (Cb) {
                __nv_bfloat162 v0 = __floats2bfloat162_rn(a[0] + b0, a[1] + b0);
                __nv_bfloat162 v1 = __floats2bfloat162_rn(a[2] + b1, a[3] + b1);
                *reinterpret_cast<__nv_bfloat162*>(Cb + off0) = v0;
                *reinterpret_cast<__nv_bfloat162*>(Cb + off1) = v1;
            } else {
                float2 r0 = make_float2(0.f, 0.f), r1 = make_float2(0.f, 0.f);
                if (res) { r0 = *(const float2*)(res + off0); r1 = *(const float2*)(res + off1); }
                float2 o0v = make_float2(a[0] + b0 + r0.x, a[1] + b0 + r0.y);
                float2 o1v = make_float2(a[2] + b1 + r1.x, a[3] + b1 + r1.y);
                *(float2*)(Cf + off0) = o0v;
                *(float2*)(Cf + off1) = o1v;
            }
        }
    }
    #undef ISSUE_TILE
}

// ---------------- spatial softmaxes (bf16 in/out, fp32 math) ----------------
__global__ __launch_bounds__(128) void softmax_q(bf16* __restrict__ p)
{
    int n = blockIdx.x * 128 + threadIdx.x;
    long long base = (long long)blockIdx.z * C3 * NN + (long long)blockIdx.y * Dd * NN + n;
    float v[Dd];
    #pragma unroll
    for (int d = 0; d < Dd; d++) v[d] = __bfloat162float(p[base + (long long)d * NN]);
    float m = v[0];
    #pragma unroll
    for (int d = 1; d < Dd; d++) m = fmaxf(m, v[d]);
    float s = 0.f;
    #pragma unroll
    for (int d = 0; d < Dd; d++) { v[d] = __expf(v[d] - m); s += v[d]; }
    float inv = 0.125f / s;
    #pragma unroll
    for (int d = 0; d < Dd; d++)
        p[base + (long long)d * NN] = __float2bfloat16(v[d] * inv);
}

__global__ __launch_bounds__(256) void softmax_k(bf16* __restrict__ p)
{
    bf16* row = p + (long long)blockIdx.y * C3 * NN + (long long)(Cc + blockIdx.x) * NN;
    int tid = threadIdx.x;
    float v[4];
    float m = -INFINITY;
    #pragma unroll
    for (int k = 0; k < 4; k++) { v[k] = __bfloat162float(row[tid + 256 * k]); m = fmaxf(m, v[k]); }
    __shared__ float red[8];
    #pragma unroll
    for (int o = 16; o; o >>= 1) m = fmaxf(m, __shfl_xor_sync(0xffffffffu, m, o));
    if ((tid & 31) == 0) red[tid >> 5] = m;
    __syncthreads();
    m = red[0];
    #pragma unroll
    for (int wv = 1; wv < 8; wv++) m = fmaxf(m, red[wv]);
    __syncthreads();
    float s = 0.f;
    #pragma unroll
    for (int k = 0; k < 4; k++) { v[k] = __expf(v[k] - m); s += v[k]; }
    #pragma unroll
    for (int o = 16; o; o >>= 1) s += __shfl_xor_sync(0xffffffffu, s, o);
    if ((tid & 31) == 0) red[tid >> 5] = s;
    __syncthreads();
    s = 0.f;
    #pragma unroll
    for (int wv = 0; wv < 8; wv++) s += red[wv];
    float inv = 1.f / s;
    #pragma unroll
    for (int k = 0; k < 4; k++) row[tid + 256 * k] = __float2bfloat16(v[k] * inv);
}

// ---------------- ctx (mma.sync): ctx_ed[e][d] = sum_n k[d][n] v[e][n] ----------------
__global__ __launch_bounds__(128) void ctx_mma(const bf16* __restrict__ qkv,
                                               bf16* __restrict__ ctx_ed)
{
    int h = blockIdx.x, bt = blockIdx.y;
    const bf16* kbase = qkv + (long long)bt * C3 * NN + (long long)(Cc + h * Dd) * NN;
    const bf16* vbase = qkv + (long long)bt * C3 * NN + (long long)(2 * Cc + h * Dd) * NN;

    __shared__ bf16 Ks[2][64 * 64];
    __shared__ bf16 Vs[2][64 * 64];
    uint32_t ksb = smem_u32(&Ks[0][0]);
    uint32_t vsb = smem_u32(&Vs[0][0]);

    int tid = threadIdx.x;
    int lane = tid & 31, warp = tid >> 5;
    int m0 = warp * 16;

    float acc[8][4] = {};

    #define CTX_ISSUE(c, buf) do {                                                  \
        _Pragma("unroll")                                                           \
        for (int i_ = 0; i_ < 8; i_++) {                                            \
            int idx_ = i_ * 128 + tid;                                              \
            int mat_ = idx_ >> 9;                                                   \
            int rem_ = idx_ & 511;                                                  \
            int row_ = rem_ >> 3, ch_ = rem_ & 7;                                   \
            const bf16* src_ = (mat_ ? vbase : kbase) + (long long)row_ * NN + (c) * 64 + ch_ * 8; \
            uint32_t dst_ = (mat_ ? vsb : ksb) + (buf) * 8192 + row_ * 128 + ((ch_ ^ (row_ & 7)) << 4); \
            CP_ASYNC(dst_, src_);                                                   \
        }                                                                           \
    } while (0)

    CTX_ISSUE(0, 0);
    CP_COMMIT();

    for (int c = 0; c < 16; c++) {
        CP_WAIT0();
        __syncthreads();
        if (c + 1 < 16) { CTX_ISSUE(c + 1, (c + 1) & 1); CP_COMMIT(); }
        int buf = c & 1;
        uint32_t ka = ksb + buf * 8192;
        uint32_t va = vsb + buf * 8192;
        #pragma unroll
        for (int ks = 0; ks < 4; ks++) {
            int k0 = ks * 16;
            uint32_t a0, a1, a2, a3;
            {
                int row = m0 + (lane & 15);
                int ch  = (k0 >> 3) + (lane >> 4);
                uint32_t addr = ka + row * 128 + ((ch ^ (row & 7)) << 4);
                LDSM_X4(a0, a1, a2, a3, addr);
            }
            #pragma unroll
            for (int nb = 0; nb < 4; nb++) {
                int row = nb * 16 + ((lane >> 4) << 3) + (lane & 7);
                int ch  = (k0 >> 3) + ((lane >> 3) & 1);
                uint32_t addr = va + row * 128 + ((ch ^ (row & 7)) << 4);
                uint32_t r0, r1, r2, r3;
                LDSM_X4(r0, r1, r2, r3, addr);
                MMA16816(acc[nb*2][0],   acc[nb*2][1],   acc[nb*2][2],   acc[nb*2][3],
                         a0, a1, a2, a3, r0, r1);
                MMA16816(acc[nb*2+1][0], acc[nb*2+1][1], acc[nb*2+1][2], acc[nb*2+1][3],
                         a0, a1, a2, a3, r2, r3);
            }
        }
    }
    #undef CTX_ISSUE

    bf16* cb = ctx_ed + ((long long)bt * HEADS + h) * (Dd * Dd);
    int g4 = lane >> 2, t4 = lane & 3;
    #pragma unroll
    for (int nt = 0; nt < 8; nt++) {
        int e0 = nt * 8 + t4 * 2;
        int d0 = m0 + g4;
        cb[(e0)     * Dd + d0]     = __float2bfloat16(acc[nt][0]);
        cb[(e0 + 1) * Dd + d0]     = __float2bfloat16(acc[nt][1]);
        cb[(e0)     * Dd + d0 + 8] = __float2bfloat16(acc[nt][2]);
        cb[(e0 + 1) * Dd + d0 + 8] = __float2bfloat16(acc[nt][3]);
    }
}

// ---------------- attn apply (mma.sync): out[e][n] = sum_d ctx_ed[e][d] q[d][n] ----------------
__global__ __launch_bounds__(256) void attn_apply_mma(const bf16* __restrict__ ctx_ed,
                                                      const bf16* __restrict__ qkv,
                                                      bf16* __restrict__ out)
{
    int n0 = blockIdx.x * 256, h = blockIdx.y, bt = blockIdx.z;
    const bf16* cbase = ctx_ed + ((long long)bt * HEADS + h) * (Dd * Dd);
    const bf16* qbase = qkv + (long long)bt * C3 * NN + (long long)(h * Dd) * NN;

    __shared__ bf16 Asm[64 * 64];
    __shared__ bf16 Bsm[64 * 256];
    uint32_t asb = smem_u32(&Asm[0]);
    uint32_t bsb = smem_u32(&Bsm[0]);

    int tid = threadIdx.x;
    int lane = tid & 31, warp = tid >> 5;
    int wm = warp >> 2, wn = warp & 3;

    #pragma unroll
    for (int i = 0; i < 2; i++) {
        int idx = i * 256 + tid;
        int row = idx >> 3, ch = idx & 7;
        const bf16* src = cbase + row * Dd + ch * 8;
        uint32_t dst = asb + row * 128 + ((ch ^ (row & 7)) << 4);
        CP_ASYNC(dst, src);
    }
    #pragma unroll
    for (int i = 0; i < 8; i++) {
        int idx = i * 256 + tid;
        int row = idx >> 5, ch = idx & 31;
        const bf16* src = qbase + (long long)row * NN + n0 + ch * 8;
        uint32_t dst = bsb + row * 512 + ((ch ^ (row & 7)) << 4);
        CP_ASYNC(dst, src);
    }
    CP_COMMIT();
    CP_WAIT0();
    __syncthreads();

    float acc[2][8][4] = {};
    #pragma unroll
    for (int ks = 0; ks < 4; ks++) {
        int k0 = ks * 16;
        uint32_t af[2][4];
        #pragma unroll
        for (int mt = 0; mt < 2; mt++) {
            int row = wm * 32 + mt * 16 + (lane & 15);
            int ch  = (k0 >> 3) + (lane >> 4);
            uint32_t addr = asb + row * 128 + ((ch ^ (row & 7)) << 4);
            LDSM_X4(af[mt][0], af[mt][1], af[mt][2], af[mt][3], addr);
        }
        #pragma unroll
        for (int nt = 0; nt < 8; nt++) {
            int krow = k0 + (lane & 15);
            int ncol = wn * 64 + nt * 8;
            uint32_t addr = bsb + krow * 512 + (((ncol >> 3) ^ (krow & 7)) << 4);
            uint32_t b0, b1;
            LDSM_X2T(b0, b1, addr);
            #pragma unroll
            for (int mt = 0; mt < 2; mt++)
                MMA16816(acc[mt][nt][0], acc[mt][nt][1], acc[mt][nt][2], acc[mt][nt][3],
                         af[mt][0], af[mt][1], af[mt][2], af[mt][3], b0, b1);
        }
    }

    bf16* ob = out + (long long)bt * Cc * NN + (long long)(h * Dd) * NN;
    int g4 = lane >> 2, t4 = lane & 3;
    #pragma unroll
    for (int mt = 0; mt < 2; mt++) {
        #pragma unroll
        for (int nt = 0; nt < 8; nt++) {
            int erow = wm * 32 + mt * 16 + g4;
            int col  = n0 + wn * 64 + nt * 8 + t4 * 2;
            float* a = acc[mt][nt];
            __nv_bfloat162 v0 = __floats2bfloat162_rn(a[0], a[1]);
            __nv_bfloat162 v1 = __floats2bfloat162_rn(a[2], a[3]);
            *reinterpret_cast<__nv_bfloat162*>(ob + (long long)erow * NN + col) = v0;
            *reinterpret_cast<__nv_bfloat162*>(ob + (long long)(erow + 8) * NN + col) = v1;
        }
    }
}

// ---------------- temporal attention (bf16 qkv) ----------------
#define ST 8
__global__ __launch_bounds__(128) void temporal_sim(const bf16* __restrict__ tqkv,
                                                    float* __restrict__ attn)
{
    int b = blockIdx.z, hh = blockIdx.y;
    int s0 = blockIdx.x * ST;
    __shared__ float ks[16 * 64 * (ST + 1)];
    const bf16* kb = tqkv + ((long long)b * C3 + Cc + hh * Dd) * (Tt * NN);
    int tid = threadIdx.x;
    #pragma unroll
    for (int l = 0; l < (16 * 64 * ST) / 128; l++) {
        int idx = l * 128 + tid;
        int s = idx & (ST - 1);
        int rest = idx >> 3;
        int d = rest & 63, j = rest >> 6;
        ks[rest * (ST + 1) + s] = __bfloat162float(kb[(long long)d * (Tt * NN) + j * NN + s0 + s]);
    }
    __syncthreads();
    int sl = tid & (ST - 1);
    int i  = tid >> 3;
    const bf16* qb = tqkv + ((long long)b * C3 + hh * Dd) * (Tt * NN) + (long long)i * NN + s0 + sl;
    float acc[16];
    #pragma unroll
    for (int j = 0; j < 16; j++) acc[j] = 0.f;
    for (int d = 0; d < 64; d++) {
        float qv = __bfloat162float(qb[(long long)d * (Tt * NN)]) * 0.125f;
        #pragma unroll
        for (int j = 0; j < 16; j++)
            acc[j] += qv * ks[(j * 64 + d) * (ST + 1) + sl];
    }
    float m = acc[0];
    #pragma unroll
    for (int j = 1; j < 16; j++) m = fmaxf(m, acc[j]);
    float sum = 0.f;
    #pragma unroll
    for (int j = 0; j < 16; j++) { acc[j] = __expf(acc[j] - m); sum += acc[j]; }
    float inv = 1.f / sum;
    float* ab = attn + (((long long)b * HEADS + hh) * Tt + i) * Tt * NN + s0 + sl;
    #pragma unroll
    for (int j = 0; j < 16; j++)
        ab[(long long)j * NN] = acc[j] * inv;
}

__global__ __launch_bounds__(128) void temporal_out(const bf16* __restrict__ tqkv,
                                                    const float* __restrict__ attn,
                                                    bf16* __restrict__ out)
{
    int b = blockIdx.z, hh = blockIdx.y;
    int s0 = blockIdx.x * ST;
    __shared__ float vs[16 * 64 * (ST + 1)];
    const bf16* vb = tqkv + ((long long)b * C3 + 2 * Cc + hh * Dd) * (Tt * NN);
    int tid = threadIdx.x;
    #pragma unroll
    for (int l = 0; l < (16 * 64 * ST) / 128; l++) {
        int idx = l * 128 + tid;
        int s = idx & (ST - 1);
        int rest = idx >> 3;
        int d = rest & 63, j = rest >> 6;
        vs[rest * (ST + 1) + s] = __bfloat162float(vb[(long long)d * (Tt * NN) + j * NN + s0 + s]);
    }
    __syncthreads();
    int sl = tid & (ST - 1);
    int dg = tid >> 3;
    const float* ab = attn + ((long long)b * HEADS + hh) * (Tt * Tt) * NN + s0 + sl;
    bf16* ob = out + ((long long)b * Cc + hh * Dd + dg * 4) * (Tt * NN) + s0 + sl;
    for (int i = 0; i < 16; i++) {
        float a0 = 0.f, a1 = 0.f, a2 = 0.f, a3 = 0.f;
        #pragma unroll
        for (int j = 0; j < 16; j++) {
            float av = ab[(long long)(i * 16 + j) * NN];
            a0 += av * vs[(j * 64 + dg * 4 + 0) * (ST + 1) + sl];
            a1 += av * vs[(j * 64 + dg * 4 + 1) * (ST + 1) + sl];
            a2 += av * vs[(j * 64 + dg * 4 + 2) * (ST + 1) + sl];
            a3 += av * vs[(j * 64 + dg * 4 + 3) * (ST + 1) + sl];
        }
        long long t_off = (long long)i * NN;
        ob[t_off + 0 * (long long)(Tt * NN)] = __float2bfloat16(a0);
        ob[t_off + 1 * (long long)(Tt * NN)] = __float2bfloat16(a1);
        ob[t_off + 2 * (long long)(Tt * NN)] = __float2bfloat16(a2);
        ob[t_off + 3 * (long long)(Tt * NN)] = __float2bfloat16(a3);
    }
}

// ---------------- launch ----------------
extern "C" void kernel_launch(void* const* d_in, const int* in_sizes, int n_in,
                              void* d_out, int out_size)
{
    const float* x      = (const float*)d_in[0];
    const float* w_sqkv = (const float*)d_in[1];
    const float* w_sout = (const float*)d_in[2];
    const float* b_sout = (const float*)d_in[3];
    const float* w_tqkv = (const float*)d_in[4];
    const float* w_tout = (const float*)d_in[5];
    float* out = (float*)d_out;

    bf16 *wsqkv_t, *wsout_t, *wtqkv_t, *wtout_t, *xbf, *sqkv, *ctx_ed, *sattn_bf, *h1_bf, *tqkv, *tout_bf;
    float *attnw;
    cudaGetSymbolAddress((void**)&wsqkv_t, g_wsqkv_t);
    cudaGetSymbolAddress((void**)&wsout_t, g_wsout_t);
    cudaGetSymbolAddress((void**)&wtqkv_t, g_wtqkv_t);
    cudaGetSymbolAddress((void**)&wtout_t, g_wtout_t);
    cudaGetSymbolAddress((void**)&xbf,     g_xbf);
    cudaGetSymbolAddress((void**)&sqkv,    g_sqkv);
    cudaGetSymbolAddress((void**)&ctx_ed,  g_ctx_ed);
    cudaGetSymbolAddress((void**)&sattn_bf,g_sattn_bf);
    cudaGetSymbolAddress((void**)&h1_bf,   g_h1_bf);
    cudaGetSymbolAddress((void**)&tqkv,    g_tqkv);
    cudaGetSymbolAddress((void**)&attnw,   g_attnw);
    cudaGetSymbolAddress((void**)&tout_bf, g_tout_bf);

    static int smem_set = 0;
    if (!smem_set) {
        cudaFuncSetAttribute(gemm_bf16, cudaFuncAttributeMaxDynamicSharedMemorySize, GSMEM);
        smem_set = 1;
    }

    const long long TN = (long long)Tt * NN;
    const long long XB = (long long)Cc * TN;

    int xN = Bb * Cc * Tt * NN;
    f2b_kernel<<<(xN / 4 + 255) / 256, 256>>>(x, xbf, xN);
    transpose_w_kernel<<<(C3 * Cc + 255) / 256, 256>>>(w_sqkv, wsqkv_t, C3, Cc);
    transpose_w_kernel<<<(Cc * Cc + 255) / 256, 256>>>(w_sout, wsout_t, Cc, Cc);
    transpose_w_kernel<<<(C3 * Cc + 255) / 256, 256>>>(w_tqkv, wtqkv_t, C3, Cc);
    transpose_w_kernel<<<(Cc * Cc + 255) / 256, 256>>>(w_tout, wtout_t, Cc, Cc);

    // 1) spatial qkv -> sqkv (bf16) [bt][o][n]
    gemm_bf16<<<dim3(NN / 256, C3 / 128, BT), 256, GSMEM>>>(
        wsqkv_t, xbf, nullptr, sqkv, nullptr, nullptr,
        Cc, C3, Tt,
        XB, NN, TN,
        (long long)Tt * C3 * NN, (long long)C3 * NN, NN);

    // 2-3) softmaxes (bf16)
    softmax_q<<<dim3(NN / 128, HEADS, BT), 128>>>(sqkv);
    softmax_k<<<dim3(Cc, BT), 256>>>(sqkv);

    // 4) ctx -> ctx_ed bf16 [e][d]
    ctx_mma<<<dim3(HEADS, BT), 128>>>(sqkv, ctx_ed);

    // 5) apply -> sattn bf16
    attn_apply_mma<<<dim3(NN / 256, HEADS, BT), 256>>>(ctx_ed, sqkv, sattn_bf);

    // 6) spatial proj + bias -> h1 bf16 [b][o][t][n]
    gemm_bf16<<<dim3(NN / 256, Cc / 128, BT), 256, GSMEM>>>(
        wsout_t, sattn_bf, nullptr, h1_bf, b_sout, nullptr,
        Cc, Cc, Tt,
        (long long)Tt * Cc * NN, (long long)Cc * NN, NN,
        XB, NN, TN);

    // 7) temporal qkv -> tqkv bf16 [b][o][tn]
    gemm_bf16<<<dim3((int)(TN / 256), C3 / 128, Bb), 256, GSMEM>>>(
        wtqkv_t, h1_bf, nullptr, tqkv, nullptr, nullptr,
        Cc, C3, 1,
        XB, 0, TN,
        (long long)C3 * TN, 0, TN);

    // 8-9) temporal attention
    temporal_sim<<<dim3(NN / ST, HEADS, Bb), 128>>>(tqkv, attnw);
    temporal_out<<<dim3(NN / ST, HEADS, Bb), 128>>>(tqkv, attnw, tout_bf);

    // 10) temporal proj + residual -> out fp32
    gemm_bf16<<<dim3((int)(TN / 256), Cc / 128, Bb), 256, GSMEM>>>(
        wtout_t, tout_bf, out, nullptr, nullptr, x,
        Cc, Cc, 1,
        XB, 0, TN,
        XB, 0, TN);
}

// round 7
// speedup vs baseline: 1.1532x; 1.1532x over previous
#include <cuda_runtime.h>
#include <cuda_bf16.h>
#include <math.h>
#include <stdint.h>

#define Bb 2
#define Cc 512
#define Tt 16
#define NN 1024
#define HEADS 8
#define Dd 64
#define BT 32
#define C3 1536

typedef __nv_bfloat16 bf16;

// ---------------- scratch (device globals) ----------------
__device__ __align__(16) bf16  g_wsqkv_t[Cc * C3];   // Wt[k][o] bf16
__device__ __align__(16) bf16  g_wsout_t[Cc * Cc];
__device__ __align__(16) bf16  g_wtqkv_t[Cc * C3];
__device__ __align__(16) bf16  g_wtout_t[Cc * Cc];
__device__ __align__(16) bf16  g_xbf[Bb * Cc * Tt * NN];
__device__ __align__(16) bf16  g_sqkv[BT * C3 * NN];
__device__ __align__(16) bf16  g_ctx_ed[BT * HEADS * Dd * Dd];
__device__ __align__(16) bf16  g_sattn_bf[BT * Cc * NN];
__device__ __align__(16) bf16  g_h1_bf[Bb * Cc * Tt * NN];
__device__ __align__(16) bf16  g_tqkv[Bb * C3 * Tt * NN];
__device__ __align__(16) bf16  g_tout_bf[Bb * Cc * Tt * NN];

// ---------------- helpers ----------------
__device__ __forceinline__ uint32_t smem_u32(const void* p) {
    uint32_t a;
    asm("{ .reg .u64 t; cvta.to.shared.u64 t, %1; cvt.u32.u64 %0, t; }" : "=r"(a) : "l"(p));
    return a;
}
#define CP_ASYNC(dst, src) asm volatile("cp.async.cg.shared.global [%0],[%1],16;\n" :: "r"(dst), "l"(src) : "memory")
#define CP_COMMIT()        asm volatile("cp.async.commit_group;\n" ::: "memory")
#define CP_WAIT0()         asm volatile("cp.async.wait_group 0;\n" ::: "memory")
#define CP_WAIT1()         asm volatile("cp.async.wait_group 1;\n" ::: "memory")

#define LDSM_X4(r0,r1,r2,r3,addr) \
    asm volatile("ldmatrix.sync.aligned.m8n8.x4.shared.b16 {%0,%1,%2,%3},[%4];" \
                 : "=r"(r0),"=r"(r1),"=r"(r2),"=r"(r3) : "r"(addr))
#define LDSM_X4T(r0,r1,r2,r3,addr) \
    asm volatile("ldmatrix.sync.aligned.m8n8.x4.trans.shared.b16 {%0,%1,%2,%3},[%4];" \
                 : "=r"(r0),"=r"(r1),"=r"(r2),"=r"(r3) : "r"(addr))
#define LDSM_X2T(r0,r1,addr) \
    asm volatile("ldmatrix.sync.aligned.m8n8.x2.trans.shared.b16 {%0,%1},[%2];" \
                 : "=r"(r0),"=r"(r1) : "r"(addr))
#define MMA16816(d0,d1,d2,d3,a0,a1,a2,a3,b0,b1) \
    asm volatile("mma.sync.aligned.m16n8k16.row.col.f32.bf16.bf16.f32 " \
                 "{%0,%1,%2,%3},{%4,%5,%6,%7},{%8,%9},{%0,%1,%2,%3};" \
                 : "+f"(d0),"+f"(d1),"+f"(d2),"+f"(d3) \
                 : "r"(a0),"r"(a1),"r"(a2),"r"(a3),"r"(b0),"r"(b1))

// ---------------- conversions ----------------
__global__ void f2b_kernel(const float* __restrict__ in, bf16* __restrict__ out, int n)
{
    int i = (blockIdx.x * blockDim.x + threadIdx.x) * 4;
    if (i < n) {
        float4 v = *(const float4*)(in + i);
        __nv_bfloat162 p0 = __floats2bfloat162_rn(v.x, v.y);
        __nv_bfloat162 p1 = __floats2bfloat162_rn(v.z, v.w);
        uint2 u;
        u.x = *(uint32_t*)&p0;
        u.y = *(uint32_t*)&p1;
        *(uint2*)(out + i) = u;
    }
}

// one launch converts + transposes all four weights (K = Cc for all)
__global__ void conv_weights(const float* __restrict__ w1, const float* __restrict__ w2,
                             const float* __restrict__ w3, const float* __restrict__ w4,
                             bf16* __restrict__ o1, bf16* __restrict__ o2,
                             bf16* __restrict__ o3, bf16* __restrict__ o4)
{
    const int N1 = C3 * Cc, N2 = Cc * Cc;
    int idx = blockIdx.x * blockDim.x + threadIdx.x;
    const float* in; bf16* out; int O; int rem;
    if (idx < N1)                { in = w1; out = o1; O = C3; rem = idx; }
    else if (idx < N1 + N2)      { in = w2; out = o2; O = Cc; rem = idx - N1; }
    else if (idx < 2 * N1 + N2)  { in = w3; out = o3; O = C3; rem = idx - N1 - N2; }
    else if (idx < 2 * (N1 + N2)){ in = w4; out = o4; O = Cc; rem = idx - 2 * N1 - N2; }
    else return;
    int o = rem % O, k = rem / O;
    out[rem] = __float2bfloat16(in[(long long)o * Cc + k]);
}

// ---------------- bf16 tensor-core GEMM (round-4 version, 128x128x32, 3-stage) ----------------
__global__ __launch_bounds__(256, 2) void gemm_bf16(
    const bf16* __restrict__ Wt,   // [K][ldA]
    const bf16* __restrict__ X,
    float* __restrict__ Cf,
    bf16* __restrict__ Cb,
    const float* __restrict__ bias,
    const float* __restrict__ res,
    int K, int ldA, int gDiv,
    long long xOuter, long long xInner, long long xRow,
    long long cOuter, long long cInner, long long cRow)
{
    __shared__ bf16 As[3][32][128];
    __shared__ bf16 Bs[3][32][128];

    int g = blockIdx.z;
    long long gq = g / gDiv, gr = g % gDiv;
    const bf16* Xb = X + gq * xOuter + gr * xInner;
    long long cbase = gq * cOuter + gr * cInner;

    int n0 = blockIdx.x * 128;
    int o0 = blockIdx.y * 128;

    int tid = threadIdx.x;
    int lane = tid & 31, warp = tid >> 5;
    int wm = warp >> 2, wn = warp & 3;

    uint32_t asb = smem_u32(&As[0][0][0]);
    uint32_t bsb = smem_u32(&Bs[0][0][0]);

    float acc[4][4][4];
    #pragma unroll
    for (int a = 0; a < 4; a++)
        #pragma unroll
        for (int b = 0; b < 4; b++)
            #pragma unroll
            for (int c = 0; c < 4; c++) acc[a][b][c] = 0.f;

    int nkt = K / 32;

    #define ISSUE_TILE(kt, buf) do {                                                     \
        int k0_ = (kt) * 32;                                                             \
        _Pragma("unroll")                                                                \
        for (int i_ = 0; i_ < 2; i_++) {                                                 \
            int idx_ = tid + 256 * i_;                                                   \
            int row_ = idx_ >> 4, ch_ = idx_ & 15;                                       \
            const bf16* sA = Wt + (long long)(k0_ + row_) * ldA + o0 + ch_ * 8;          \
            uint32_t dA = asb + (buf) * 8192 + row_ * 256 + (((ch_) ^ (row_ & 7)) << 4); \
            CP_ASYNC(dA, sA);                                                            \
            const bf16* sB = Xb + (long long)(k0_ + row_) * xRow + n0 + ch_ * 8;         \
            uint32_t dB = bsb + (buf) * 8192 + row_ * 256 + (((ch_) ^ (row_ & 7)) << 4); \
            CP_ASYNC(dB, sB);                                                            \
        }                                                                                \
    } while (0)

    ISSUE_TILE(0, 0);
    CP_COMMIT();
    ISSUE_TILE(1, 1);
    CP_COMMIT();

    int r7 = lane & 7, sub = lane >> 3;
    int brow_lo = lane & 15;

    for (int kt = 0; kt < nkt; kt++) {
        CP_WAIT1();
        __syncthreads();
        if (kt + 2 < nkt) {
            int nb = (kt + 2) % 3;
            ISSUE_TILE(kt + 2, nb);
        }
        CP_COMMIT();
        int buf = kt % 3;
        uint32_t abase = asb + buf * 8192;
        uint32_t bbase = bsb + buf * 8192;

        #pragma unroll
        for (int ks = 0; ks < 2; ks++) {
            uint32_t af[4][4];
            uint32_t bf_[4][2];
            #pragma unroll
            for (int mt = 0; mt < 4; mt++) {
                int krow = ks * 16 + r7 + ((sub >> 1) << 3);
                int mcol = wm * 64 + mt * 16 + ((sub & 1) << 3);
                uint32_t addr = abase + krow * 256 + ((((mcol >> 3)) ^ (krow & 7)) << 4);
                LDSM_X4T(af[mt][0], af[mt][1], af[mt][2], af[mt][3], addr);
            }
            #pragma unroll
            for (int nt = 0; nt < 4; nt++) {
                int brow = ks * 16 + brow_lo;
                int ncol = wn * 32 + nt * 8;
                uint32_t addr = bbase + brow * 256 + ((((ncol >> 3)) ^ (brow & 7)) << 4);
                LDSM_X2T(bf_[nt][0], bf_[nt][1], addr);
            }
            #pragma unroll
            for (int mt = 0; mt < 4; mt++)
                #pragma unroll
                for (int nt = 0; nt < 4; nt++)
                    MMA16816(acc[mt][nt][0], acc[mt][nt][1], acc[mt][nt][2], acc[mt][nt][3],
                             af[mt][0], af[mt][1], af[mt][2], af[mt][3],
                             bf_[nt][0], bf_[nt][1]);
        }
    }

    int g4 = lane >> 2, t4 = lane & 3;
    #pragma unroll
    for (int mt = 0; mt < 4; mt++) {
        #pragma unroll
        for (int nt = 0; nt < 4; nt++) {
            int orow = o0 + wm * 64 + mt * 16 + g4;
            int col  = n0 + wn * 32 + nt * 8 + t4 * 2;
            long long off0 = cbase + (long long)orow * cRow + col;
            long long off1 = off0 + 8 * cRow;
            float b0 = bias ? bias[orow] : 0.f;
            float b1 = bias ? bias[orow + 8] : 0.f;
            float* a = acc[mt][nt];
            if (Cb) {
                __nv_bfloat162 v0 = __floats2bfloat162_rn(a[0] + b0, a[1] + b0);
                __nv_bfloat162 v1 = __floats2bfloat162_rn(a[2] + b1, a[3] + b1);
                *reinterpret_cast<__nv_bfloat162*>(Cb + off0) = v0;
                *reinterpret_cast<__nv_bfloat162*>(Cb + off1) = v1;
            } else {
                float2 r0 = make_float2(0.f, 0.f), r1 = make_float2(0.f, 0.f);
                if (res) { r0 = *(const float2*)(res + off0); r1 = *(const float2*)(res + off1); }
                float2 o0v = make_float2(a[0] + b0 + r0.x, a[1] + b0 + r0.y);
                float2 o1v = make_float2(a[2] + b1 + r1.x, a[3] + b1 + r1.y);
                *(float2*)(Cf + off0) = o0v;
                *(float2*)(Cf + off1) = o1v;
            }
        }
    }
    #undef ISSUE_TILE
}

// ---------------- spatial softmaxes (bf16 in/out, fp32 math) ----------------
__global__ __launch_bounds__(128) void softmax_q(bf16* __restrict__ p)
{
    int n = blockIdx.x * 128 + threadIdx.x;
    long long base = (long long)blockIdx.z * C3 * NN + (long long)blockIdx.y * Dd * NN + n;
    float v[Dd];
    #pragma unroll
    for (int d = 0; d < Dd; d++) v[d] = __bfloat162float(p[base + (long long)d * NN]);
    float m = v[0];
    #pragma unroll
    for (int d = 1; d < Dd; d++) m = fmaxf(m, v[d]);
    float s = 0.f;
    #pragma unroll
    for (int d = 0; d < Dd; d++) { v[d] = __expf(v[d] - m); s += v[d]; }
    float inv = 0.125f / s;
    #pragma unroll
    for (int d = 0; d < Dd; d++)
        p[base + (long long)d * NN] = __float2bfloat16(v[d] * inv);
}

__global__ __launch_bounds__(256) void softmax_k(bf16* __restrict__ p)
{
    bf16* row = p + (long long)blockIdx.y * C3 * NN + (long long)(Cc + blockIdx.x) * NN;
    int tid = threadIdx.x;
    float v[4];
    float m = -INFINITY;
    #pragma unroll
    for (int k = 0; k < 4; k++) { v[k] = __bfloat162float(row[tid + 256 * k]); m = fmaxf(m, v[k]); }
    __shared__ float red[8];
    #pragma unroll
    for (int o = 16; o; o >>= 1) m = fmaxf(m, __shfl_xor_sync(0xffffffffu, m, o));
    if ((tid & 31) == 0) red[tid >> 5] = m;
    __syncthreads();
    m = red[0];
    #pragma unroll
    for (int wv = 1; wv < 8; wv++) m = fmaxf(m, red[wv]);
    __syncthreads();
    float s = 0.f;
    #pragma unroll
    for (int k = 0; k < 4; k++) { v[k] = __expf(v[k] - m); s += v[k]; }
    #pragma unroll
    for (int o = 16; o; o >>= 1) s += __shfl_xor_sync(0xffffffffu, s, o);
    if ((tid & 31) == 0) red[tid >> 5] = s;
    __syncthreads();
    s = 0.f;
    #pragma unroll
    for (int wv = 0; wv < 8; wv++) s += red[wv];
    float inv = 1.f / s;
    #pragma unroll
    for (int k = 0; k < 4; k++) row[tid + 256 * k] = __float2bfloat16(v[k] * inv);
}

// ---------------- ctx (mma.sync): ctx_ed[e][d] = sum_n k[d][n] v[e][n] ----------------
__global__ __launch_bounds__(128) void ctx_mma(const bf16* __restrict__ qkv,
                                               bf16* __restrict__ ctx_ed)
{
    int h = blockIdx.x, bt = blockIdx.y;
    const bf16* kbase = qkv + (long long)bt * C3 * NN + (long long)(Cc + h * Dd) * NN;
    const bf16* vbase = qkv + (long long)bt * C3 * NN + (long long)(2 * Cc + h * Dd) * NN;

    __shared__ bf16 Ks[2][64 * 64];
    __shared__ bf16 Vs[2][64 * 64];
    uint32_t ksb = smem_u32(&Ks[0][0]);
    uint32_t vsb = smem_u32(&Vs[0][0]);

    int tid = threadIdx.x;
    int lane = tid & 31, warp = tid >> 5;
    int m0 = warp * 16;

    float acc[8][4] = {};

    #define CTX_ISSUE(c, buf) do {                                                  \
        _Pragma("unroll")                                                           \
        for (int i_ = 0; i_ < 8; i_++) {                                            \
            int idx_ = i_ * 128 + tid;                                              \
            int mat_ = idx_ >> 9;                                                   \
            int rem_ = idx_ & 511;                                                  \
            int row_ = rem_ >> 3, ch_ = rem_ & 7;                                   \
            const bf16* src_ = (mat_ ? vbase : kbase) + (long long)row_ * NN + (c) * 64 + ch_ * 8; \
            uint32_t dst_ = (mat_ ? vsb : ksb) + (buf) * 8192 + row_ * 128 + ((ch_ ^ (row_ & 7)) << 4); \
            CP_ASYNC(dst_, src_);                                                   \
        }                                                                           \
    } while (0)

    CTX_ISSUE(0, 0);
    CP_COMMIT();

    for (int c = 0; c < 16; c++) {
        CP_WAIT0();
        __syncthreads();
        if (c + 1 < 16) { CTX_ISSUE(c + 1, (c + 1) & 1); CP_COMMIT(); }
        int buf = c & 1;
        uint32_t ka = ksb + buf * 8192;
        uint32_t va = vsb + buf * 8192;
        #pragma unroll
        for (int ks = 0; ks < 4; ks++) {
            int k0 = ks * 16;
            uint32_t a0, a1, a2, a3;
            {
                int row = m0 + (lane & 15);
                int ch  = (k0 >> 3) + (lane >> 4);
                uint32_t addr = ka + row * 128 + ((ch ^ (row & 7)) << 4);
                LDSM_X4(a0, a1, a2, a3, addr);
            }
            #pragma unroll
            for (int nb = 0; nb < 4; nb++) {
                int row = nb * 16 + ((lane >> 4) << 3) + (lane & 7);
                int ch  = (k0 >> 3) + ((lane >> 3) & 1);
                uint32_t addr = va + row * 128 + ((ch ^ (row & 7)) << 4);
                uint32_t r0, r1, r2, r3;
                LDSM_X4(r0, r1, r2, r3, addr);
                MMA16816(acc[nb*2][0],   acc[nb*2][1],   acc[nb*2][2],   acc[nb*2][3],
                         a0, a1, a2, a3, r0, r1);
                MMA16816(acc[nb*2+1][0], acc[nb*2+1][1], acc[nb*2+1][2], acc[nb*2+1][3],
                         a0, a1, a2, a3, r2, r3);
            }
        }
    }
    #undef CTX_ISSUE

    bf16* cb = ctx_ed + ((long long)bt * HEADS + h) * (Dd * Dd);
    int g4 = lane >> 2, t4 = lane & 3;
    #pragma unroll
    for (int nt = 0; nt < 8; nt++) {
        int e0 = nt * 8 + t4 * 2;
        int d0 = m0 + g4;
        cb[(e0)     * Dd + d0]     = __float2bfloat16(acc[nt][0]);
        cb[(e0 + 1) * Dd + d0]     = __float2bfloat16(acc[nt][1]);
        cb[(e0)     * Dd + d0 + 8] = __float2bfloat16(acc[nt][2]);
        cb[(e0 + 1) * Dd + d0 + 8] = __float2bfloat16(acc[nt][3]);
    }
}

// ---------------- attn apply (mma.sync): out[e][n] = sum_d ctx_ed[e][d] q[d][n] ----------------
__global__ __launch_bounds__(256) void attn_apply_mma(const bf16* __restrict__ ctx_ed,
                                                      const bf16* __restrict__ qkv,
                                                      bf16* __restrict__ out)
{
    int n0 = blockIdx.x * 256, h = blockIdx.y, bt = blockIdx.z;
    const bf16* cbase = ctx_ed + ((long long)bt * HEADS + h) * (Dd * Dd);
    const bf16* qbase = qkv + (long long)bt * C3 * NN + (long long)(h * Dd) * NN;

    __shared__ bf16 Asm[64 * 64];
    __shared__ bf16 Bsm[64 * 256];
    uint32_t asb = smem_u32(&Asm[0]);
    uint32_t bsb = smem_u32(&Bsm[0]);

    int tid = threadIdx.x;
    int lane = tid & 31, warp = tid >> 5;
    int wm = warp >> 2, wn = warp & 3;

    #pragma unroll
    for (int i = 0; i < 2; i++) {
        int idx = i * 256 + tid;
        int row = idx >> 3, ch = idx & 7;
        const bf16* src = cbase + row * Dd + ch * 8;
        uint32_t dst = asb + row * 128 + ((ch ^ (row & 7)) << 4);
        CP_ASYNC(dst, src);
    }
    #pragma unroll
    for (int i = 0; i < 8; i++) {
        int idx = i * 256 + tid;
        int row = idx >> 5, ch = idx & 31;
        const bf16* src = qbase + (long long)row * NN + n0 + ch * 8;
        uint32_t dst = bsb + row * 512 + ((ch ^ (row & 7)) << 4);
        CP_ASYNC(dst, src);
    }
    CP_COMMIT();
    CP_WAIT0();
    __syncthreads();

    float acc[2][8][4] = {};
    #pragma unroll
    for (int ks = 0; ks < 4; ks++) {
        int k0 = ks * 16;
        uint32_t af[2][4];
        #pragma unroll
        for (int mt = 0; mt < 2; mt++) {
            int row = wm * 32 + mt * 16 + (lane & 15);
            int ch  = (k0 >> 3) + (lane >> 4);
            uint32_t addr = asb + row * 128 + ((ch ^ (row & 7)) << 4);
            LDSM_X4(af[mt][0], af[mt][1], af[mt][2], af[mt][3], addr);
        }
        #pragma unroll
        for (int nt = 0; nt < 8; nt++) {
            int krow = k0 + (lane & 15);
            int ncol = wn * 64 + nt * 8;
            uint32_t addr = bsb + krow * 512 + (((ncol >> 3) ^ (krow & 7)) << 4);
            uint32_t b0, b1;
            LDSM_X2T(b0, b1, addr);
            #pragma unroll
            for (int mt = 0; mt < 2; mt++)
                MMA16816(acc[mt][nt][0], acc[mt][nt][1], acc[mt][nt][2], acc[mt][nt][3],
                         af[mt][0], af[mt][1], af[mt][2], af[mt][3], b0, b1);
        }
    }

    bf16* ob = out + (long long)bt * Cc * NN + (long long)(h * Dd) * NN;
    int g4 = lane >> 2, t4 = lane & 3;
    #pragma unroll
    for (int mt = 0; mt < 2; mt++) {
        #pragma unroll
        for (int nt = 0; nt < 8; nt++) {
            int erow = wm * 32 + mt * 16 + g4;
            int col  = n0 + wn * 64 + nt * 8 + t4 * 2;
            float* a = acc[mt][nt];
            __nv_bfloat162 v0 = __floats2bfloat162_rn(a[0], a[1]);
            __nv_bfloat162 v1 = __floats2bfloat162_rn(a[2], a[3]);
            *reinterpret_cast<__nv_bfloat162*>(ob + (long long)erow * NN + col) = v0;
            *reinterpret_cast<__nv_bfloat162*>(ob + (long long)(erow + 8) * NN + col) = v1;
        }
    }
}

// ---------------- fused temporal attention ----------------
// One kernel: sim + softmax + apply, attention weights kept in smem.
#define ST 8
#define TSMEM (2 * 16 * 64 * 9 * 4 + 256 * 9 * 4)   // ks + vs + attw = 82944 B

__global__ __launch_bounds__(128) void temporal_fused(const bf16* __restrict__ tqkv,
                                                      bf16* __restrict__ out)
{
    extern __shared__ float tsm[];
    float* ks   = tsm;                     // [16*64][9]
    float* vs   = tsm + 16 * 64 * 9;       // [16*64][9]
    float* attw = vs  + 16 * 64 * 9;       // [256][9]

    int b = blockIdx.z, hh = blockIdx.y;
    int s0 = blockIdx.x * ST;
    const bf16* kb = tqkv + ((long long)b * C3 + Cc + hh * Dd) * (Tt * NN);
    const bf16* vb = tqkv + ((long long)b * C3 + 2 * Cc + hh * Dd) * (Tt * NN);
    int tid = threadIdx.x;

    #pragma unroll
    for (int l = 0; l < (16 * 64 * ST) / 128; l++) {
        int idx = l * 128 + tid;
        int s = idx & (ST - 1);
        int rest = idx >> 3;                  // j*64+d
        int d = rest & 63, j = rest >> 6;
        long long goff = (long long)d * (Tt * NN) + j * NN + s0 + s;
        ks[rest * 9 + s] = __bfloat162float(kb[goff]);
        vs[rest * 9 + s] = __bfloat162float(vb[goff]);
    }
    __syncthreads();

    int sl = tid & (ST - 1);
    int i  = tid >> 3;                        // phase-1: query time index

    // phase 1: sim + softmax
    {
        const bf16* qb = tqkv + ((long long)b * C3 + hh * Dd) * (Tt * NN)
                       + (long long)i * NN + s0 + sl;
        float acc[16];
        #pragma unroll
        for (int j = 0; j < 16; j++) acc[j] = 0.f;
        for (int d = 0; d < 64; d++) {
            float qv = __bfloat162float(qb[(long long)d * (Tt * NN)]) * 0.125f;
            #pragma unroll
            for (int j = 0; j < 16; j++)
                acc[j] += qv * ks[(j * 64 + d) * 9 + sl];
        }
        float m = acc[0];
        #pragma unroll
        for (int j = 1; j < 16; j++) m = fmaxf(m, acc[j]);
        float sum = 0.f;
        #pragma unroll
        for (int j = 0; j < 16; j++) { acc[j] = __expf(acc[j] - m); sum += acc[j]; }
        float inv = 1.f / sum;
        #pragma unroll
        for (int j = 0; j < 16; j++)
            attw[(i * 16 + j) * 9 + sl] = acc[j] * inv;
    }
    __syncthreads();

    // phase 2: out[c=h*64+dg*4..+3][t=ii][s] = sum_j attw[ii][j] * v[j][d]
    int dg = i;                               // reuse tid>>3 as d-group
    bf16* ob = out + ((long long)b * Cc + hh * Dd + dg * 4) * (Tt * NN) + s0 + sl;
    for (int ii = 0; ii < 16; ii++) {
        float a0 = 0.f, a1 = 0.f, a2 = 0.f, a3 = 0.f;
        #pragma unroll
        for (int j = 0; j < 16; j++) {
            float av = attw[(ii * 16 + j) * 9 + sl];
            a0 += av * vs[(j * 64 + dg * 4 + 0) * 9 + sl];
            a1 += av * vs[(j * 64 + dg * 4 + 1) * 9 + sl];
            a2 += av * vs[(j * 64 + dg * 4 + 2) * 9 + sl];
            a3 += av * vs[(j * 64 + dg * 4 + 3) * 9 + sl];
        }
        long long t_off = (long long)ii * NN;
        ob[t_off + 0 * (long long)(Tt * NN)] = __float2bfloat16(a0);
        ob[t_off + 1 * (long long)(Tt * NN)] = __float2bfloat16(a1);
        ob[t_off + 2 * (long long)(Tt * NN)] = __float2bfloat16(a2);
        ob[t_off + 3 * (long long)(Tt * NN)] = __float2bfloat16(a3);
    }
}

// ---------------- launch ----------------
extern "C" void kernel_launch(void* const* d_in, const int* in_sizes, int n_in,
                              void* d_out, int out_size)
{
    const float* x      = (const float*)d_in[0];
    const float* w_sqkv = (const float*)d_in[1];
    const float* w_sout = (const float*)d_in[2];
    const float* b_sout = (const float*)d_in[3];
    const float* w_tqkv = (const float*)d_in[4];
    const float* w_tout = (const float*)d_in[5];
    float* out = (float*)d_out;

    bf16 *wsqkv_t, *wsout_t, *wtqkv_t, *wtout_t, *xbf, *sqkv, *ctx_ed, *sattn_bf, *h1_bf, *tqkv, *tout_bf;
    cudaGetSymbolAddress((void**)&wsqkv_t, g_wsqkv_t);
    cudaGetSymbolAddress((void**)&wsout_t, g_wsout_t);
    cudaGetSymbolAddress((void**)&wtqkv_t, g_wtqkv_t);
    cudaGetSymbolAddress((void**)&wtout_t, g_wtout_t);
    cudaGetSymbolAddress((void**)&xbf,     g_xbf);
    cudaGetSymbolAddress((void**)&sqkv,    g_sqkv);
    cudaGetSymbolAddress((void**)&ctx_ed,  g_ctx_ed);
    cudaGetSymbolAddress((void**)&sattn_bf,g_sattn_bf);
    cudaGetSymbolAddress((void**)&h1_bf,   g_h1_bf);
    cudaGetSymbolAddress((void**)&tqkv,    g_tqkv);
    cudaGetSymbolAddress((void**)&tout_bf, g_tout_bf);

    static int attr_set = 0;
    if (!attr_set) {
        cudaFuncSetAttribute(temporal_fused, cudaFuncAttributeMaxDynamicSharedMemorySize, TSMEM);
        attr_set = 1;
    }

    const long long TN = (long long)Tt * NN;
    const long long XB = (long long)Cc * TN;

    int xN = Bb * Cc * Tt * NN;
    f2b_kernel<<<(xN / 4 + 255) / 256, 256>>>(x, xbf, xN);
    conv_weights<<<(2 * (C3 * Cc + Cc * Cc) + 255) / 256, 256>>>(
        w_sqkv, w_sout, w_tqkv, w_tout, wsqkv_t, wsout_t, wtqkv_t, wtout_t);

    // 1) spatial qkv -> sqkv (bf16) [bt][o][n]
    gemm_bf16<<<dim3(NN / 128, C3 / 128, BT), 256>>>(
        wsqkv_t, xbf, nullptr, sqkv, nullptr, nullptr,
        Cc, C3, Tt,
        XB, NN, TN,
        (long long)Tt * C3 * NN, (long long)C3 * NN, NN);

    // 2-3) softmaxes (bf16)
    softmax_q<<<dim3(NN / 128, HEADS, BT), 128>>>(sqkv);
    softmax_k<<<dim3(Cc, BT), 256>>>(sqkv);

    // 4) ctx -> ctx_ed bf16 [e][d]
    ctx_mma<<<dim3(HEADS, BT), 128>>>(sqkv, ctx_ed);

    // 5) apply -> sattn bf16
    attn_apply_mma<<<dim3(NN / 256, HEADS, BT), 256>>>(ctx_ed, sqkv, sattn_bf);

    // 6) spatial proj + bias -> h1 bf16 [b][o][t][n]
    gemm_bf16<<<dim3(NN / 128, Cc / 128, BT), 256>>>(
        wsout_t, sattn_bf, nullptr, h1_bf, b_sout, nullptr,
        Cc, Cc, Tt,
        (long long)Tt * Cc * NN, (long long)Cc * NN, NN,
        XB, NN, TN);

    // 7) temporal qkv -> tqkv bf16 [b][o][tn]
    gemm_bf16<<<dim3((int)(TN / 128), C3 / 128, Bb), 256>>>(
        wtqkv_t, h1_bf, nullptr, tqkv, nullptr, nullptr,
        Cc, C3, 1,
        XB, 0, TN,
        (long long)C3 * TN, 0, TN);

    // 8) fused temporal attention -> tout bf16
    temporal_fused<<<dim3(NN / ST, HEADS, Bb), 128, TSMEM>>>(tqkv, tout_bf);

    // 9) temporal proj + residual -> out fp32
    gemm_bf16<<<dim3((int)(TN / 128), Cc / 128, Bb), 256>>>(
        wtout_t, tout_bf, out, nullptr, nullptr, x,
        Cc, Cc, 1,
        XB, 0, TN,
        XB, 0, TN);
}